// round 1
// baseline (speedup 1.0000x reference)
#include <cuda_runtime.h>
#include <math.h>

#define Bv 64
#define Tv 512
#define Iv 1024
#define Hv 1024
#define Gv 4096   // 4*H

// ---------------------------------------------------------------------------
// Static device scratch (allocation-free per harness rules)
// ---------------------------------------------------------------------------
__device__ float g_Gx[(size_t)Tv * Bv * Gv];   // 512 MB: precomputed x@Wih^T + b, layout [T][B][4H]
__device__ float g_h[2][Bv * Hv];              // double-buffered hidden state
__device__ float g_c[Bv * Hv];                 // cell state (in-place, per-block-disjoint columns)

__device__ __forceinline__ float sigmoidf_(float x) {
    return 1.0f / (1.0f + expf(-x));
}

// ---------------------------------------------------------------------------
// Zero-init state
// ---------------------------------------------------------------------------
__global__ void init_state_kernel() {
    int i = blockIdx.x * blockDim.x + threadIdx.x;
    if (i < Bv * Hv) {
        g_h[0][i] = 0.0f;
        g_c[i]    = 0.0f;
    }
}

// ---------------------------------------------------------------------------
// Input GEMM: Gx[t][b][n] = sum_k x[b][t][k] * Wih[n][k] + bias[n]
// Tiled fp32 SGEMM: 128x128 block tile, BK=8, 256 threads, 8x8 per thread.
// M = B*T = 32768 rows (row m -> b = m/T, t = m%T), N = 4096, K = 1024.
// ---------------------------------------------------------------------------
__global__ __launch_bounds__(256) void gemm_in_kernel(
    const float* __restrict__ x,
    const float* __restrict__ Wih,
    const float* __restrict__ bias)
{
    __shared__ float As[8][128];
    __shared__ float Bs[8][128];

    const int tid = threadIdx.x;
    const int m0 = blockIdx.y * 128;
    const int n0 = blockIdx.x * 128;
    const int tx = tid & 15;       // 0..15 -> 8 output cols
    const int ty = tid >> 4;       // 0..15 -> 8 output rows

    // Each thread loads one float4 of A and one float4 of B per K-tile.
    const int lrow  = tid >> 1;        // 0..127
    const int lcol4 = (tid & 1) * 4;   // 0 or 4

    const float* Aptr = x   + (size_t)(m0 + lrow) * Iv;
    const float* Bptr = Wih + (size_t)(n0 + lrow) * Iv;

    float acc[8][8];
    #pragma unroll
    for (int i = 0; i < 8; i++)
        #pragma unroll
        for (int j = 0; j < 8; j++)
            acc[i][j] = 0.0f;

    for (int k0 = 0; k0 < Iv; k0 += 8) {
        float4 av = *(const float4*)(Aptr + k0 + lcol4);
        float4 bv = *(const float4*)(Bptr + k0 + lcol4);
        __syncthreads();
        As[lcol4 + 0][lrow] = av.x;
        As[lcol4 + 1][lrow] = av.y;
        As[lcol4 + 2][lrow] = av.z;
        As[lcol4 + 3][lrow] = av.w;
        Bs[lcol4 + 0][lrow] = bv.x;
        Bs[lcol4 + 1][lrow] = bv.y;
        Bs[lcol4 + 2][lrow] = bv.z;
        Bs[lcol4 + 3][lrow] = bv.w;
        __syncthreads();

        #pragma unroll
        for (int kk = 0; kk < 8; kk++) {
            float4 a0 = *(const float4*)(&As[kk][ty * 8]);
            float4 a1 = *(const float4*)(&As[kk][ty * 8 + 4]);
            float4 b0 = *(const float4*)(&Bs[kk][tx * 8]);
            float4 b1 = *(const float4*)(&Bs[kk][tx * 8 + 4]);
            float a[8] = {a0.x, a0.y, a0.z, a0.w, a1.x, a1.y, a1.z, a1.w};
            float b[8] = {b0.x, b0.y, b0.z, b0.w, b1.x, b1.y, b1.z, b1.w};
            #pragma unroll
            for (int i = 0; i < 8; i++)
                #pragma unroll
                for (int j = 0; j < 8; j++)
                    acc[i][j] += a[i] * b[j];
        }
    }

    // Write with row remap into [T][B][4H] layout, adding bias.
    #pragma unroll
    for (int i = 0; i < 8; i++) {
        int m = m0 + ty * 8 + i;
        int bidx = m / Tv;
        int tt   = m % Tv;
        float* orow = g_Gx + ((size_t)tt * Bv + bidx) * Gv + n0 + tx * 8;
        const float* brow = bias + n0 + tx * 8;
        #pragma unroll
        for (int j = 0; j < 8; j++)
            orow[j] = acc[i][j] + brow[j];
    }
}

// ---------------------------------------------------------------------------
// One LSTM timestep. 128 blocks x 256 threads.
// Block owns 8 hidden columns (hc0..hc0+7) across all 4 gates -> a [64 x 32]
// slice of the gate matrix:  gates = Gx[t] + h_in @ Whh^T.
// Then fused elementwise cell update + output write.
// ---------------------------------------------------------------------------
__global__ __launch_bounds__(256) void lstm_step_kernel(
    const float* __restrict__ Whh,
    float* __restrict__ dout,
    int t)
{
    __shared__ float Hs[64][33];   // h tile: [row][kk]
    __shared__ float Ws[32][34];   // W tile: [j][kk], j = gate*8 + jc
    __shared__ float Gb[64][33];   // computed gates slice

    const int tid = threadIdx.x;
    const int hc0 = blockIdx.x * 8;

    const float* __restrict__ h_in = g_h[t & 1];
    float* __restrict__ h_out      = g_h[(t + 1) & 1];

    const int cg = tid & 15;   // column pair: j = 2*cg, 2*cg+1
    const int rg = tid >> 4;   // row group: rows 4*rg .. 4*rg+3
    const int lane = tid & 31;
    const int wgrp = tid >> 5; // 0..7

    float acc[4][2];
    #pragma unroll
    for (int r = 0; r < 4; r++) {
        int row = rg * 4 + r;
        #pragma unroll
        for (int c = 0; c < 2; c++) {
            int j = cg * 2 + c;
            int gate = j >> 3;
            int jc   = j & 7;
            acc[r][c] = g_Gx[((size_t)t * Bv + row) * Gv + gate * Hv + hc0 + jc];
        }
    }

    for (int k0 = 0; k0 < Hv; k0 += 32) {
        __syncthreads();
        // Load h tile: 64 rows x 32 k (coalesced, conflict-free STS)
        #pragma unroll
        for (int p = 0; p < 8; p++) {
            int row = wgrp + p * 8;
            Hs[row][lane] = h_in[row * Hv + k0 + lane];
        }
        // Load Whh tile: 32 gate-rows x 32 k
        #pragma unroll
        for (int p = 0; p < 4; p++) {
            int j = wgrp + p * 8;
            int gate = j >> 3;
            int jc   = j & 7;
            Ws[j][lane] = Whh[(size_t)(gate * Hv + hc0 + jc) * Hv + k0 + lane];
        }
        __syncthreads();

        #pragma unroll
        for (int kk = 0; kk < 32; kk++) {
            float w0 = Ws[cg * 2 + 0][kk];
            float w1 = Ws[cg * 2 + 1][kk];
            #pragma unroll
            for (int r = 0; r < 4; r++) {
                float hv = Hs[rg * 4 + r][kk];
                acc[r][0] += hv * w0;
                acc[r][1] += hv * w1;
            }
        }
    }

    // Stage gate slice to smem for the per-(row,col) cell update.
    #pragma unroll
    for (int r = 0; r < 4; r++)
        #pragma unroll
        for (int c = 0; c < 2; c++)
            Gb[rg * 4 + r][cg * 2 + c] = acc[r][c];
    __syncthreads();

    #pragma unroll
    for (int it = tid; it < 512; it += 256) {
        int row = it >> 3;    // batch index 0..63
        int jc  = it & 7;     // hidden-col offset 0..7
        float ig = Gb[row][jc];
        float fg = Gb[row][8 + jc];
        float gg = Gb[row][16 + jc];
        float og = Gb[row][24 + jc];

        int hidx = row * Hv + hc0 + jc;
        float c_old = g_c[hidx];
        float cn = sigmoidf_(fg) * c_old + sigmoidf_(ig) * tanhf(gg);
        float hn = sigmoidf_(og) * tanhf(cn);

        g_c[hidx]   = cn;
        h_out[hidx] = hn;

        // outputs [B][T][H]
        dout[(size_t)row * Tv * Hv + (size_t)t * Hv + hc0 + jc] = hn;
        if (t == Tv - 1) {
            size_t base = (size_t)Bv * Tv * Hv;
            dout[base + hidx] = hn;                         // h_T [B][H]
            dout[base + (size_t)Bv * Hv + hidx] = cn;       // c_T [B][H]
        }
    }
}

// ---------------------------------------------------------------------------
// Launch
// ---------------------------------------------------------------------------
extern "C" void kernel_launch(void* const* d_in, const int* in_sizes, int n_in,
                              void* d_out, int out_size)
{
    const float* x    = (const float*)d_in[0];  // [B, T, I]
    const float* Wih  = (const float*)d_in[1];  // [4H, I]
    const float* Whh  = (const float*)d_in[2];  // [4H, H]
    const float* bias = (const float*)d_in[3];  // [4H]
    float* out = (float*)d_out;

    (void)in_sizes; (void)n_in; (void)out_size;

    init_state_kernel<<<(Bv * Hv + 255) / 256, 256>>>();

    dim3 ggrid(Gv / 128, (Bv * Tv) / 128);   // (32, 256)
    gemm_in_kernel<<<ggrid, 256>>>(x, Wih, bias);

    for (int t = 0; t < Tv; t++) {
        lstm_step_kernel<<<Hv / 8, 256>>>(Whh, out, t);
    }
}

// round 4
// speedup vs baseline: 2.0620x; 2.0620x over previous
#include <cuda_runtime.h>
#include <cuda_bf16.h>
#include <cstdint>
#include <math.h>

#define Bv 64
#define Tv 512
#define Iv 1024
#define Hv 1024
#define Gv 4096   // 4*H

// ---------------------------------------------------------------------------
// Static device scratch
// ---------------------------------------------------------------------------
__device__ float g_Gx[(size_t)Tv * Bv * Gv];              // 512MB [T][B][4H]
__device__ __nv_bfloat16 g_x_hi[(size_t)Bv * Tv * Iv];    // 64MB
__device__ __nv_bfloat16 g_x_lo[(size_t)Bv * Tv * Iv];    // 64MB
__device__ __nv_bfloat16 g_Wih_hi[(size_t)Gv * Iv];       // 8MB
__device__ __nv_bfloat16 g_Wih_lo[(size_t)Gv * Iv];
__device__ __nv_bfloat16 g_Whh_hi[(size_t)Gv * Hv];       // 8MB
__device__ __nv_bfloat16 g_Whh_lo[(size_t)Gv * Hv];
__device__ __nv_bfloat16 g_h_hi[2][Bv * Hv];
__device__ __nv_bfloat16 g_h_lo[2][Bv * Hv];
__device__ float g_c[Bv * Hv];

// ---------------------------------------------------------------------------
// Helpers
// ---------------------------------------------------------------------------
__device__ __forceinline__ uint32_t smem_u32(const void* p) {
    uint32_t a;
    asm("{ .reg .u64 t; cvta.to.shared.u64 t, %1; cvt.u32.u64 %0, t; }"
        : "=r"(a) : "l"(p));
    return a;
}

#define SWZ128(o) ((o) ^ (((o) >> 3) & 0x70))

__device__ __forceinline__ void cp16(uint32_t dst, const void* src) {
    asm volatile("cp.async.cg.shared.global [%0], [%1], 16;" :: "r"(dst), "l"(src));
}
#define CP_COMMIT() asm volatile("cp.async.commit_group;" ::: "memory")
#define CP_WAIT(n)  asm volatile("cp.async.wait_group %0;" :: "n"(n) : "memory")

__device__ __forceinline__ void ldsm4(uint32_t* r, uint32_t addr) {
    asm volatile("ldmatrix.sync.aligned.m8n8.x4.shared.b16 {%0,%1,%2,%3}, [%4];"
        : "=r"(r[0]), "=r"(r[1]), "=r"(r[2]), "=r"(r[3]) : "r"(addr));
}

__device__ __forceinline__ void mma16816(float* d, const uint32_t* a,
                                         uint32_t b0, uint32_t b1) {
    asm volatile(
        "mma.sync.aligned.m16n8k16.row.col.f32.bf16.bf16.f32 "
        "{%0,%1,%2,%3}, {%4,%5,%6,%7}, {%8,%9}, {%0,%1,%2,%3};"
        : "+f"(d[0]), "+f"(d[1]), "+f"(d[2]), "+f"(d[3])
        : "r"(a[0]), "r"(a[1]), "r"(a[2]), "r"(a[3]), "r"(b0), "r"(b1));
}

__device__ __forceinline__ float sigm(float x) { return 1.0f / (1.0f + expf(-x)); }

// ---------------------------------------------------------------------------
// Shared warp-level 3-pass split-bf16 MMA over one K-chunk of 64.
// Warp tile: m32 x (NT*16). A tiles 128B rows (64 bf16), B tiles same.
// acc layout: acc[m*(2*NT) + jb*2 + p][4]
// ---------------------------------------------------------------------------
template <int NT>
__device__ __forceinline__ void warp_mma_chunk(
    uint32_t aHi, uint32_t aLo, uint32_t bHi, uint32_t bLo,
    int mrow, int nbase, int lane, float acc[][4])
{
    const int arowoff = (lane & 7) + ((lane >> 3) & 1) * 8;
    const int nrowoff = (lane & 7) + ((lane >> 4) & 1) * 8;
    #pragma unroll
    for (int kk = 0; kk < 4; kk++) {
        uint32_t ah[2][4], al[2][4], bh[NT][4], bl[NT][4];
        const int akoff = kk * 32 + (lane >> 4) * 16;          // bytes
        const int bkoff = kk * 32 + ((lane >> 3) & 1) * 16;    // bytes
        #pragma unroll
        for (int m = 0; m < 2; m++) {
            uint32_t off = SWZ128((uint32_t)((mrow + m * 16 + arowoff) * 128 + akoff));
            ldsm4(ah[m], aHi + off);
            ldsm4(al[m], aLo + off);
        }
        #pragma unroll
        for (int jb = 0; jb < NT; jb++) {
            uint32_t off = SWZ128((uint32_t)((nbase + jb * 16 + nrowoff) * 128 + bkoff));
            ldsm4(bh[jb], bHi + off);
            ldsm4(bl[jb], bLo + off);
        }
        // pass 1: hi * W_hi
        #pragma unroll
        for (int jb = 0; jb < NT; jb++)
            #pragma unroll
            for (int m = 0; m < 2; m++) {
                mma16816(acc[m * 2 * NT + jb * 2],     ah[m], bh[jb][0], bh[jb][1]);
                mma16816(acc[m * 2 * NT + jb * 2 + 1], ah[m], bh[jb][2], bh[jb][3]);
            }
        // pass 2: lo * W_hi
        #pragma unroll
        for (int jb = 0; jb < NT; jb++)
            #pragma unroll
            for (int m = 0; m < 2; m++) {
                mma16816(acc[m * 2 * NT + jb * 2],     al[m], bh[jb][0], bh[jb][1]);
                mma16816(acc[m * 2 * NT + jb * 2 + 1], al[m], bh[jb][2], bh[jb][3]);
            }
        // pass 3: hi * W_lo
        #pragma unroll
        for (int jb = 0; jb < NT; jb++)
            #pragma unroll
            for (int m = 0; m < 2; m++) {
                mma16816(acc[m * 2 * NT + jb * 2],     ah[m], bl[jb][0], bl[jb][1]);
                mma16816(acc[m * 2 * NT + jb * 2 + 1], ah[m], bl[jb][2], bl[jb][3]);
            }
    }
}

// ---------------------------------------------------------------------------
// Prep kernels. NOTE: destinations are __device__ symbols and MUST be bound
// inside device code (passing them as host-side kernel args passes the host
// shadow address — the R3 bug that silently zeroed all MMA operands).
// ---------------------------------------------------------------------------
__global__ void split_kernel(const float* __restrict__ src, int which, size_t n) {
    __nv_bfloat16* hi;
    __nv_bfloat16* lo;
    if (which == 0)      { hi = g_x_hi;   lo = g_x_lo;   }
    else if (which == 1) { hi = g_Wih_hi; lo = g_Wih_lo; }
    else                 { hi = g_Whh_hi; lo = g_Whh_lo; }
    size_t stride = (size_t)gridDim.x * blockDim.x;
    for (size_t i = (size_t)blockIdx.x * blockDim.x + threadIdx.x; i < n; i += stride) {
        float v = src[i];
        __nv_bfloat16 h = __float2bfloat16(v);
        hi[i] = h;
        lo[i] = __float2bfloat16(v - __bfloat162float(h));
    }
}

__global__ void init_state_kernel() {
    int i = blockIdx.x * blockDim.x + threadIdx.x;
    if (i < Bv * Hv) {
        g_h_hi[0][i] = __float2bfloat16(0.0f);
        g_h_lo[0][i] = __float2bfloat16(0.0f);
        g_c[i] = 0.0f;
    }
}

// ---------------------------------------------------------------------------
// Input GEMM (HMMA): Gx[t][b][n] = x[b,t,:] . Wih[n,:] + bias[n]
// CTA tile 128x128, 8 warps (4 m x 2 n), warp m32 x n64. K=1024, chunks of 64.
// ---------------------------------------------------------------------------
#define G_STAGE 65536
#define G_SMEM  (2 * G_STAGE)

__device__ __forceinline__ void gemm_load(uint32_t sb, int s, int k0,
                                          int m0, int n0, int tid) {
    uint32_t base = sb + (uint32_t)s * G_STAGE;
    #pragma unroll
    for (int r = 0; r < 8; r++) {         // A: 2048 cp16 (hi+lo)
        int idx = tid + r * 256;
        int hf = idx >> 10, rem = idx & 1023;
        int row = rem >> 3, c = rem & 7;
        const __nv_bfloat16* src = (hf ? g_x_lo : g_x_hi)
                                   + (size_t)(m0 + row) * Iv + k0 + c * 8;
        cp16(base + hf * 16384 + SWZ128((uint32_t)(row * 128 + c * 16)), src);
    }
    #pragma unroll
    for (int r = 0; r < 8; r++) {         // B: 2048 cp16 (hi+lo)
        int idx = tid + r * 256;
        int hf = idx >> 10, rem = idx & 1023;
        int row = rem >> 3, c = rem & 7;
        const __nv_bfloat16* src = (hf ? g_Wih_lo : g_Wih_hi)
                                   + (size_t)(n0 + row) * Iv + k0 + c * 8;
        cp16(base + 32768 + hf * 16384 + SWZ128((uint32_t)(row * 128 + c * 16)), src);
    }
}

__global__ void __launch_bounds__(256, 1) gemm_in_mma(const float* __restrict__ bias)
{
    extern __shared__ char smem[];
    uint32_t sb = smem_u32(smem);
    const int tid = threadIdx.x, lane = tid & 31, wid = tid >> 5;
    const int m0 = blockIdx.y * 128, n0 = blockIdx.x * 128;

    float acc[16][4];
    #pragma unroll
    for (int i = 0; i < 16; i++)
        #pragma unroll
        for (int j = 0; j < 4; j++) acc[i][j] = 0.0f;

    gemm_load(sb, 0, 0, m0, n0, tid);
    CP_COMMIT();

    const int mrow = (wid & 3) * 32, nbase = (wid >> 2) * 64;
    for (int it = 0; it < 16; it++) {
        const int s = it & 1;
        if (it + 1 < 16) {
            gemm_load(sb, (it + 1) & 1, (it + 1) * 64, m0, n0, tid);
            CP_COMMIT();
            CP_WAIT(1);
        } else {
            CP_WAIT(0);
        }
        __syncthreads();
        uint32_t base = sb + (uint32_t)s * G_STAGE;
        warp_mma_chunk<4>(base, base + 16384, base + 32768, base + 49152,
                          mrow, nbase, lane, acc);
        __syncthreads();
    }

    // Epilogue: remap rows to [T][B][4H], add bias.
    #pragma unroll
    for (int m = 0; m < 2; m++)
        #pragma unroll
        for (int j = 0; j < 8; j++) {
            float* a = acc[m * 8 + j];
            int gr = m0 + (wid & 3) * 32 + m * 16 + (lane >> 2);
            int n  = n0 + (wid >> 2) * 64 + j * 8 + 2 * (lane & 3);
            float b0 = bias[n], b1 = bias[n + 1];
            int bi0 = gr >> 9, tt0 = gr & 511;
            float* o0 = g_Gx + ((size_t)tt0 * Bv + bi0) * Gv + n;
            o0[0] = a[0] + b0; o0[1] = a[1] + b1;
            int gr2 = gr + 8, bi2 = gr2 >> 9, tt2 = gr2 & 511;
            float* o2 = g_Gx + ((size_t)tt2 * Bv + bi2) * Gv + n;
            o2[0] = a[2] + b0; o2[1] = a[3] + b1;
        }
}

// ---------------------------------------------------------------------------
// LSTM step (HMMA). 64 CTAs x 128 threads. CTA = M64 x N64 (16 hid cols x 4 gates).
// 4 warps (2 m x 2 n), warp m32 x n32.
// ---------------------------------------------------------------------------
#define S_STAGE 32768
#define S_GS    (2 * S_STAGE)
#define S_SMEM  (S_GS + 64 * 68 * 4)

__device__ __forceinline__ void step_load(uint32_t sb, int s, int k0, int j0,
                                          const __nv_bfloat16* __restrict__ hHi,
                                          const __nv_bfloat16* __restrict__ hLo,
                                          int tid) {
    uint32_t base = sb + (uint32_t)s * S_STAGE;
    #pragma unroll
    for (int r = 0; r < 8; r++) {         // A (h): 1024 cp16
        int idx = tid + r * 128;
        int hf = idx >> 9, rem = idx & 511;
        int row = rem >> 3, c = rem & 7;
        const __nv_bfloat16* src = (hf ? hLo : hHi) + (size_t)row * Hv + k0 + c * 8;
        cp16(base + hf * 8192 + SWZ128((uint32_t)(row * 128 + c * 16)), src);
    }
    #pragma unroll
    for (int r = 0; r < 8; r++) {         // W: 1024 cp16 (64 rows: gate*16+jc)
        int idx = tid + r * 128;
        int hf = idx >> 9, rem = idx & 511;
        int row = rem >> 3, c = rem & 7;
        int wrow = (row >> 4) * Hv + j0 + (row & 15);
        const __nv_bfloat16* src = (hf ? g_Whh_lo : g_Whh_hi)
                                   + (size_t)wrow * Hv + k0 + c * 8;
        cp16(base + 16384 + hf * 8192 + SWZ128((uint32_t)(row * 128 + c * 16)), src);
    }
}

__global__ void __launch_bounds__(128, 1) lstm_step_mma(float* __restrict__ dout, int t)
{
    extern __shared__ char smem[];
    uint32_t sb = smem_u32(smem);
    const int tid = threadIdx.x, lane = tid & 31, wid = tid >> 5;
    const int j0 = blockIdx.x * 16;
    const __nv_bfloat16* hHi = g_h_hi[t & 1];
    const __nv_bfloat16* hLo = g_h_lo[t & 1];
    __nv_bfloat16* hHiN = g_h_hi[(t + 1) & 1];
    __nv_bfloat16* hLoN = g_h_lo[(t + 1) & 1];

    float acc[8][4];
    #pragma unroll
    for (int i = 0; i < 8; i++)
        #pragma unroll
        for (int j = 0; j < 4; j++) acc[i][j] = 0.0f;

    step_load(sb, 0, 0, j0, hHi, hLo, tid);
    CP_COMMIT();

    const int mrow = (wid & 1) * 32, nbase = (wid >> 1) * 32;
    for (int it = 0; it < 16; it++) {
        const int s = it & 1;
        if (it + 1 < 16) {
            step_load(sb, (it + 1) & 1, (it + 1) * 64, j0, hHi, hLo, tid);
            CP_COMMIT();
            CP_WAIT(1);
        } else {
            CP_WAIT(0);
        }
        __syncthreads();
        uint32_t base = sb + (uint32_t)s * S_STAGE;
        warp_mma_chunk<2>(base, base + 8192, base + 16384, base + 24576,
                          mrow, nbase, lane, acc);
        __syncthreads();
    }

    // Stage gates to SMEM (64 rows x 64 cols, pad 68)
    float* Gs = (float*)(smem + S_GS);
    #pragma unroll
    for (int m = 0; m < 2; m++)
        #pragma unroll
        for (int j = 0; j < 4; j++) {
            float* a = acc[m * 4 + j];
            int r0 = mrow + m * 16 + (lane >> 2);
            int cc = nbase + j * 8 + 2 * (lane & 3);
            Gs[r0 * 68 + cc]       = a[0];
            Gs[r0 * 68 + cc + 1]   = a[1];
            Gs[(r0 + 8) * 68 + cc]     = a[2];
            Gs[(r0 + 8) * 68 + cc + 1] = a[3];
        }
    __syncthreads();

    // Fused cell update: 1024 cells (64 batch x 16 hidden cols)
    #pragma unroll
    for (int p = 0; p < 8; p++) {
        int cell = tid + p * 128;
        int b = cell >> 4, jc = cell & 15;
        const float* gxr = g_Gx + ((size_t)t * Bv + b) * Gv + j0 + jc;
        float gi = Gs[b * 68 + jc]      + gxr[0];
        float gf = Gs[b * 68 + 16 + jc] + gxr[1024];
        float gg = Gs[b * 68 + 32 + jc] + gxr[2048];
        float go = Gs[b * 68 + 48 + jc] + gxr[3072];

        int hidx = b * Hv + j0 + jc;
        float c_old = g_c[hidx];
        float cn = sigm(gf) * c_old + sigm(gi) * tanhf(gg);
        float hn = sigm(go) * tanhf(cn);
        g_c[hidx] = cn;

        __nv_bfloat16 hi = __float2bfloat16(hn);
        hHiN[hidx] = hi;
        hLoN[hidx] = __float2bfloat16(hn - __bfloat162float(hi));

        dout[(size_t)b * Tv * Hv + (size_t)t * Hv + j0 + jc] = hn;
        if (t == Tv - 1) {
            size_t obase = (size_t)Bv * Tv * Hv;
            dout[obase + hidx] = hn;                       // h_T
            dout[obase + (size_t)Bv * Hv + hidx] = cn;     // c_T
        }
    }
}

// ---------------------------------------------------------------------------
// Launch
// ---------------------------------------------------------------------------
extern "C" void kernel_launch(void* const* d_in, const int* in_sizes, int n_in,
                              void* d_out, int out_size)
{
    const float* x    = (const float*)d_in[0];  // [B, T, I]
    const float* Wih  = (const float*)d_in[1];  // [4H, I]
    const float* Whh  = (const float*)d_in[2];  // [4H, H]
    const float* bias = (const float*)d_in[3];  // [4H]
    float* out = (float*)d_out;
    (void)in_sizes; (void)n_in; (void)out_size;

    cudaFuncSetAttribute(gemm_in_mma,  cudaFuncAttributeMaxDynamicSharedMemorySize, G_SMEM);
    cudaFuncSetAttribute(lstm_step_mma, cudaFuncAttributeMaxDynamicSharedMemorySize, S_SMEM);

    split_kernel<<<8192, 256>>>(x,   0, (size_t)Bv * Tv * Iv);
    split_kernel<<<4096, 256>>>(Wih, 1, (size_t)Gv * Iv);
    split_kernel<<<4096, 256>>>(Whh, 2, (size_t)Gv * Hv);
    init_state_kernel<<<(Bv * Hv + 255) / 256, 256>>>();

    dim3 ggrid(Gv / 128, (Bv * Tv) / 128);   // (32, 256)
    gemm_in_mma<<<ggrid, 256, G_SMEM>>>(bias);

    for (int t = 0; t < Tv; t++) {
        lstm_step_mma<<<64, 128, S_SMEM>>>(out, t);
    }
}

// round 5
// speedup vs baseline: 3.2712x; 1.5864x over previous
#include <cuda_runtime.h>
#include <cuda_bf16.h>
#include <cstdint>
#include <math.h>

#define Bv 64
#define Tv 512
#define Iv 1024
#define Hv 1024
#define Gv 4096   // 4*H

// ---------------------------------------------------------------------------
// Static device scratch
// ---------------------------------------------------------------------------
__device__ float g_Gx[(size_t)Tv * Bv * Gv];              // 512MB [T][B][4H]
__device__ __nv_bfloat16 g_x_hi[(size_t)Bv * Tv * Iv];    // 64MB
__device__ __nv_bfloat16 g_x_lo[(size_t)Bv * Tv * Iv];    // 64MB
__device__ __nv_bfloat16 g_Wih_hi[(size_t)Gv * Iv];       // 8MB
__device__ __nv_bfloat16 g_Wih_lo[(size_t)Gv * Iv];
__device__ __nv_bfloat16 g_Whh_hi[(size_t)Gv * Hv];       // 8MB
__device__ __nv_bfloat16 g_Whh_lo[(size_t)Gv * Hv];
__device__ __nv_bfloat16 g_h_hi[2][Bv * Hv];
__device__ __nv_bfloat16 g_h_lo[2][Bv * Hv];
__device__ float g_c[Bv * Hv];
__device__ unsigned int g_bar;

// ---------------------------------------------------------------------------
// Helpers
// ---------------------------------------------------------------------------
__device__ __forceinline__ uint32_t smem_u32(const void* p) {
    uint32_t a;
    asm("{ .reg .u64 t; cvta.to.shared.u64 t, %1; cvt.u32.u64 %0, t; }"
        : "=r"(a) : "l"(p));
    return a;
}

#define SWZ128(o) ((o) ^ (((o) >> 3) & 0x70))

__device__ __forceinline__ void cp16(uint32_t dst, const void* src) {
    asm volatile("cp.async.cg.shared.global [%0], [%1], 16;" :: "r"(dst), "l"(src));
}
#define CP_COMMIT() asm volatile("cp.async.commit_group;" ::: "memory")
#define CP_WAIT(n)  asm volatile("cp.async.wait_group %0;" :: "n"(n) : "memory")

__device__ __forceinline__ void ldsm4(uint32_t* r, uint32_t addr) {
    asm volatile("ldmatrix.sync.aligned.m8n8.x4.shared.b16 {%0,%1,%2,%3}, [%4];"
        : "=r"(r[0]), "=r"(r[1]), "=r"(r[2]), "=r"(r[3]) : "r"(addr));
}

__device__ __forceinline__ void mma16816(float* d, const uint32_t* a,
                                         uint32_t b0, uint32_t b1) {
    asm volatile(
        "mma.sync.aligned.m16n8k16.row.col.f32.bf16.bf16.f32 "
        "{%0,%1,%2,%3}, {%4,%5,%6,%7}, {%8,%9}, {%0,%1,%2,%3};"
        : "+f"(d[0]), "+f"(d[1]), "+f"(d[2]), "+f"(d[3])
        : "r"(a[0]), "r"(a[1]), "r"(a[2]), "r"(a[3]), "r"(b0), "r"(b1));
}

__device__ __forceinline__ float sigm(float x) { return 1.0f / (1.0f + expf(-x)); }

// ---------------------------------------------------------------------------
// Warp-level 3-pass split-bf16 MMA over one K-chunk of 64 (proven in R4).
// Warp tile: m32 x (NT*16). acc layout: acc[m*(2*NT) + jb*2 + p][4]
// ---------------------------------------------------------------------------
template <int NT>
__device__ __forceinline__ void warp_mma_chunk(
    uint32_t aHi, uint32_t aLo, uint32_t bHi, uint32_t bLo,
    int mrow, int nbase, int lane, float acc[][4])
{
    const int arowoff = (lane & 7) + ((lane >> 3) & 1) * 8;
    const int nrowoff = (lane & 7) + ((lane >> 4) & 1) * 8;
    #pragma unroll
    for (int kk = 0; kk < 4; kk++) {
        uint32_t ah[2][4], al[2][4], bh[NT][4], bl[NT][4];
        const int akoff = kk * 32 + (lane >> 4) * 16;          // bytes
        const int bkoff = kk * 32 + ((lane >> 3) & 1) * 16;    // bytes
        #pragma unroll
        for (int m = 0; m < 2; m++) {
            uint32_t off = SWZ128((uint32_t)((mrow + m * 16 + arowoff) * 128 + akoff));
            ldsm4(ah[m], aHi + off);
            ldsm4(al[m], aLo + off);
        }
        #pragma unroll
        for (int jb = 0; jb < NT; jb++) {
            uint32_t off = SWZ128((uint32_t)((nbase + jb * 16 + nrowoff) * 128 + bkoff));
            ldsm4(bh[jb], bHi + off);
            ldsm4(bl[jb], bLo + off);
        }
        #pragma unroll
        for (int jb = 0; jb < NT; jb++)
            #pragma unroll
            for (int m = 0; m < 2; m++) {
                mma16816(acc[m * 2 * NT + jb * 2],     ah[m], bh[jb][0], bh[jb][1]);
                mma16816(acc[m * 2 * NT + jb * 2 + 1], ah[m], bh[jb][2], bh[jb][3]);
            }
        #pragma unroll
        for (int jb = 0; jb < NT; jb++)
            #pragma unroll
            for (int m = 0; m < 2; m++) {
                mma16816(acc[m * 2 * NT + jb * 2],     al[m], bh[jb][0], bh[jb][1]);
                mma16816(acc[m * 2 * NT + jb * 2 + 1], al[m], bh[jb][2], bh[jb][3]);
            }
        #pragma unroll
        for (int jb = 0; jb < NT; jb++)
            #pragma unroll
            for (int m = 0; m < 2; m++) {
                mma16816(acc[m * 2 * NT + jb * 2],     ah[m], bl[jb][0], bl[jb][1]);
                mma16816(acc[m * 2 * NT + jb * 2 + 1], ah[m], bl[jb][2], bl[jb][3]);
            }
    }
}

// ---------------------------------------------------------------------------
// Prep kernels (device symbols bound in device code — R3 lesson).
// ---------------------------------------------------------------------------
__global__ void split_kernel(const float* __restrict__ src, int which, size_t n) {
    __nv_bfloat16* hi;
    __nv_bfloat16* lo;
    if (which == 0)      { hi = g_x_hi;   lo = g_x_lo;   }
    else if (which == 1) { hi = g_Wih_hi; lo = g_Wih_lo; }
    else                 { hi = g_Whh_hi; lo = g_Whh_lo; }
    size_t stride = (size_t)gridDim.x * blockDim.x;
    for (size_t i = (size_t)blockIdx.x * blockDim.x + threadIdx.x; i < n; i += stride) {
        float v = src[i];
        __nv_bfloat16 h = __float2bfloat16(v);
        hi[i] = h;
        lo[i] = __float2bfloat16(v - __bfloat162float(h));
    }
}

__global__ void init_state_kernel() {
    int i = blockIdx.x * blockDim.x + threadIdx.x;
    if (i == 0) g_bar = 0u;
    if (i < Bv * Hv) {
        g_h_hi[0][i] = __float2bfloat16(0.0f);
        g_h_lo[0][i] = __float2bfloat16(0.0f);
        g_c[i] = 0.0f;
    }
}

// ---------------------------------------------------------------------------
// Input GEMM (HMMA, unchanged from R4 pass)
// ---------------------------------------------------------------------------
#define G_STAGE 65536
#define G_SMEM  (2 * G_STAGE)

__device__ __forceinline__ void gemm_load(uint32_t sb, int s, int k0,
                                          int m0, int n0, int tid) {
    uint32_t base = sb + (uint32_t)s * G_STAGE;
    #pragma unroll
    for (int r = 0; r < 8; r++) {
        int idx = tid + r * 256;
        int hf = idx >> 10, rem = idx & 1023;
        int row = rem >> 3, c = rem & 7;
        const __nv_bfloat16* src = (hf ? g_x_lo : g_x_hi)
                                   + (size_t)(m0 + row) * Iv + k0 + c * 8;
        cp16(base + hf * 16384 + SWZ128((uint32_t)(row * 128 + c * 16)), src);
    }
    #pragma unroll
    for (int r = 0; r < 8; r++) {
        int idx = tid + r * 256;
        int hf = idx >> 10, rem = idx & 1023;
        int row = rem >> 3, c = rem & 7;
        const __nv_bfloat16* src = (hf ? g_Wih_lo : g_Wih_hi)
                                   + (size_t)(n0 + row) * Iv + k0 + c * 8;
        cp16(base + 32768 + hf * 16384 + SWZ128((uint32_t)(row * 128 + c * 16)), src);
    }
}

__global__ void __launch_bounds__(256, 1) gemm_in_mma(const float* __restrict__ bias)
{
    extern __shared__ char smem[];
    uint32_t sb = smem_u32(smem);
    const int tid = threadIdx.x, lane = tid & 31, wid = tid >> 5;
    const int m0 = blockIdx.y * 128, n0 = blockIdx.x * 128;

    float acc[16][4];
    #pragma unroll
    for (int i = 0; i < 16; i++)
        #pragma unroll
        for (int j = 0; j < 4; j++) acc[i][j] = 0.0f;

    gemm_load(sb, 0, 0, m0, n0, tid);
    CP_COMMIT();

    const int mrow = (wid & 3) * 32, nbase = (wid >> 2) * 64;
    for (int it = 0; it < 16; it++) {
        const int s = it & 1;
        if (it + 1 < 16) {
            gemm_load(sb, (it + 1) & 1, (it + 1) * 64, m0, n0, tid);
            CP_COMMIT();
            CP_WAIT(1);
        } else {
            CP_WAIT(0);
        }
        __syncthreads();
        uint32_t base = sb + (uint32_t)s * G_STAGE;
        warp_mma_chunk<4>(base, base + 16384, base + 32768, base + 49152,
                          mrow, nbase, lane, acc);
        __syncthreads();
    }

    #pragma unroll
    for (int m = 0; m < 2; m++)
        #pragma unroll
        for (int j = 0; j < 8; j++) {
            float* a = acc[m * 8 + j];
            int gr = m0 + (wid & 3) * 32 + m * 16 + (lane >> 2);
            int n  = n0 + (wid >> 2) * 64 + j * 8 + 2 * (lane & 3);
            float b0 = bias[n], b1 = bias[n + 1];
            int bi0 = gr >> 9, tt0 = gr & 511;
            float* o0 = g_Gx + ((size_t)tt0 * Bv + bi0) * Gv + n;
            o0[0] = a[0] + b0; o0[1] = a[1] + b1;
            int gr2 = gr + 8, bi2 = gr2 >> 9, tt2 = gr2 & 511;
            float* o2 = g_Gx + ((size_t)tt2 * Bv + bi2) * Gv + n;
            o2[0] = a[2] + b0; o2[1] = a[3] + b1;
        }
}

// ---------------------------------------------------------------------------
// Persistent LSTM recurrence. 128 CTAs x 256 threads, 1 CTA/SM (all resident).
// CTA owns 8 hidden cols (32 gate rows). Whh hi+lo tile (128KB) resident in
// SMEM for all 512 steps. h streamed per step (16 chunks of K=64, 2-stage
// cp.async). 8 warps: warps 0-3 even chunks, 4-7 odd chunks; two partial gate
// buffers reduced in the fused cell update. Grid barrier between steps.
// ---------------------------------------------------------------------------
#define WS_HI 0
#define WS_LO 65536
#define AB    131072                      /* 2 stages x (hi 8KB + lo 8KB) */
#define GS0   163840                      /* 64 x 33 fp32 = 8448 */
#define GS1   172288
#define P_SMEM 180736

__device__ __forceinline__ void persist_loadA(uint32_t sb, int s, int k0,
                                              const __nv_bfloat16* __restrict__ hHi,
                                              const __nv_bfloat16* __restrict__ hLo,
                                              int tid) {
    uint32_t base = sb + AB + (uint32_t)s * 16384;
    #pragma unroll
    for (int r = 0; r < 4; r++) {          // 1024 cp16 = 16KB
        int idx = tid + r * 256;
        int hf = idx >> 9, rem = idx & 511;
        int row = rem >> 3, c = rem & 7;   // row = batch 0..63
        const __nv_bfloat16* src = (hf ? hLo : hHi) + (size_t)row * Hv + k0 + c * 8;
        cp16(base + hf * 8192 + SWZ128((uint32_t)(row * 128 + c * 16)), src);
    }
}

__global__ void __launch_bounds__(256, 1) lstm_persistent(float* __restrict__ dout)
{
    extern __shared__ char smem[];
    uint32_t sb = smem_u32(smem);
    const int tid = threadIdx.x, lane = tid & 31, wid = tid >> 5;
    const int j0 = blockIdx.x * 8;
    const int par = wid >> 2;                  // k-parity this warp computes
    const int mrow = (wid & 1) * 32;
    const int nbase = ((wid >> 1) & 1) * 16;

    // ---- Preload Whh hi+lo tile: 32 gate rows x K=1024, swizzled, chunk-major
    #pragma unroll
    for (int r = 0; r < 32; r++) {             // 8192 cp16 = 128KB
        int idx = tid + r * 256;
        int hf = idx >> 12, rem = idx & 4095;
        int chunk = rem >> 8, within = rem & 255;
        int row = within >> 3, c = within & 7; // row = gate*8 + jc
        int gate = row >> 3, jc = row & 7;
        const __nv_bfloat16* src = (hf ? g_Whh_lo : g_Whh_hi)
            + (size_t)(gate * Hv + j0 + jc) * Hv + chunk * 64 + c * 8;
        cp16(sb + (hf ? WS_LO : WS_HI) + chunk * 4096
                + SWZ128((uint32_t)(row * 128 + c * 16)), src);
    }
    CP_COMMIT();
    CP_WAIT(0);
    __syncthreads();

    float* Gs0 = (float*)(smem + GS0);
    float* Gs1 = (float*)(smem + GS1);

    for (int t = 0; t < Tv; t++) {
        const __nv_bfloat16* hHi = g_h_hi[t & 1];
        const __nv_bfloat16* hLo = g_h_lo[t & 1];
        __nv_bfloat16* hHiN = g_h_hi[(t + 1) & 1];
        __nv_bfloat16* hLoN = g_h_lo[(t + 1) & 1];

        float acc[4][4];
        #pragma unroll
        for (int i = 0; i < 4; i++)
            #pragma unroll
            for (int j = 0; j < 4; j++) acc[i][j] = 0.0f;

        persist_loadA(sb, 0, 0, hHi, hLo, tid);
        CP_COMMIT();

        for (int it = 0; it < 16; it++) {
            const int s = it & 1;
            if (it + 1 < 16) {
                persist_loadA(sb, s ^ 1, (it + 1) * 64, hHi, hLo, tid);
                CP_COMMIT();
                CP_WAIT(1);
            } else {
                CP_WAIT(0);
            }
            __syncthreads();
            if ((it & 1) == par) {
                uint32_t aHi = sb + AB + (uint32_t)s * 16384;
                warp_mma_chunk<1>(aHi, aHi + 8192,
                                  sb + WS_HI + (uint32_t)it * 4096,
                                  sb + WS_LO + (uint32_t)it * 4096,
                                  mrow, nbase, lane, acc);
            }
            __syncthreads();
        }

        // Stage partial gates (each k-parity half to its own buffer)
        float* Gs = par ? Gs1 : Gs0;
        #pragma unroll
        for (int m = 0; m < 2; m++)
            #pragma unroll
            for (int p = 0; p < 2; p++) {
                float* a = acc[m * 2 + p];
                int r0 = mrow + m * 16 + (lane >> 2);
                int cc = nbase + p * 8 + 2 * (lane & 3);
                Gs[r0 * 33 + cc]           = a[0];
                Gs[r0 * 33 + cc + 1]       = a[1];
                Gs[(r0 + 8) * 33 + cc]     = a[2];
                Gs[(r0 + 8) * 33 + cc + 1] = a[3];
            }
        __syncthreads();

        // Fused cell update: 512 cells (64 batch x 8 hidden cols)
        #pragma unroll
        for (int p = 0; p < 2; p++) {
            int cell = tid + p * 256;
            int b = cell >> 3, jc = cell & 7;
            const float* gxr = g_Gx + ((size_t)t * Bv + b) * Gv + j0 + jc;
            float gi = Gs0[b * 33 + jc]      + Gs1[b * 33 + jc]      + gxr[0];
            float gf = Gs0[b * 33 + 8 + jc]  + Gs1[b * 33 + 8 + jc]  + gxr[1024];
            float gg = Gs0[b * 33 + 16 + jc] + Gs1[b * 33 + 16 + jc] + gxr[2048];
            float go = Gs0[b * 33 + 24 + jc] + Gs1[b * 33 + 24 + jc] + gxr[3072];

            int hidx = b * Hv + j0 + jc;
            float c_old = g_c[hidx];
            float cn = sigm(gf) * c_old + sigm(gi) * tanhf(gg);
            float hn = sigm(go) * tanhf(cn);
            g_c[hidx] = cn;

            __nv_bfloat16 hi = __float2bfloat16(hn);
            hHiN[hidx] = hi;
            hLoN[hidx] = __float2bfloat16(hn - __bfloat162float(hi));

            dout[(size_t)b * Tv * Hv + (size_t)t * Hv + j0 + jc] = hn;
            if (t == Tv - 1) {
                size_t obase = (size_t)Bv * Tv * Hv;
                dout[obase + hidx] = hn;                    // h_T
                dout[obase + (size_t)Bv * Hv + hidx] = cn;  // c_T
            }
        }

        // ---- Grid barrier (release-arrive by tid0, acquire-spin, CTA fanout)
        __syncthreads();
        if (tid == 0) {
            unsigned int ignored;
            asm volatile("atom.add.release.gpu.u32 %0, [%1], 1;"
                         : "=r"(ignored) : "l"(&g_bar) : "memory");
            unsigned int target = 128u * (unsigned int)(t + 1);
            unsigned int cur;
            do {
                asm volatile("ld.acquire.gpu.u32 %0, [%1];"
                             : "=r"(cur) : "l"(&g_bar) : "memory");
                if (cur >= target) break;
                asm volatile("nanosleep.u32 64;");
            } while (true);
        }
        __syncthreads();
    }
}

// ---------------------------------------------------------------------------
// Launch
// ---------------------------------------------------------------------------
extern "C" void kernel_launch(void* const* d_in, const int* in_sizes, int n_in,
                              void* d_out, int out_size)
{
    const float* x    = (const float*)d_in[0];  // [B, T, I]
    const float* Wih  = (const float*)d_in[1];  // [4H, I]
    const float* Whh  = (const float*)d_in[2];  // [4H, H]
    const float* bias = (const float*)d_in[3];  // [4H]
    float* out = (float*)d_out;
    (void)in_sizes; (void)n_in; (void)out_size;

    cudaFuncSetAttribute(gemm_in_mma,     cudaFuncAttributeMaxDynamicSharedMemorySize, G_SMEM);
    cudaFuncSetAttribute(lstm_persistent, cudaFuncAttributeMaxDynamicSharedMemorySize, P_SMEM);

    split_kernel<<<8192, 256>>>(x,   0, (size_t)Bv * Tv * Iv);
    split_kernel<<<4096, 256>>>(Wih, 1, (size_t)Gv * Iv);
    split_kernel<<<4096, 256>>>(Whh, 2, (size_t)Gv * Hv);
    init_state_kernel<<<(Bv * Hv + 255) / 256, 256>>>();

    dim3 ggrid(Gv / 128, (Bv * Tv) / 128);   // (32, 256)
    gemm_in_mma<<<ggrid, 256, G_SMEM>>>(bias);

    lstm_persistent<<<128, 256, P_SMEM>>>(out);
}